// round 4
// baseline (speedup 1.0000x reference)
#include <cuda_runtime.h>
#include <cstdint>
#include <math_constants.h>

#define NI   1024
#define NC   201
#define TT   100
#define ROW  (NC * TT)          // 20100
#define GRID 740                // persistent blocks + work queue (occupancy-safe)

// -------- scratch (no allocations; zero at module load) --------
__device__ float          g_v[NI * NC];     // deferred per-(n,c) v for bg rows
__device__ double         g_part[NI];       // per-row weighted sum (non-bg), 0 for bg
__device__ unsigned char  g_isbg[NI];
__device__ int            g_next;           // row work queue (reset by tail)
__device__ int            g_done;           // block completion counter (reset by tail)

// ======================= threefry2x32 (JAX-exact) =======================
__host__ __device__ constexpr uint32_t rotl32(uint32_t x, int r) {
    return (x << r) | (x >> (32 - r));
}
struct TF2 { uint32_t a, b; };

__host__ __device__ constexpr TF2 tf2x32(uint32_t k0, uint32_t k1,
                                         uint32_t x0, uint32_t x1) {
    uint32_t ks2 = k0 ^ k1 ^ 0x1BD11BDAu;
    uint32_t kk[3] = {k0, k1, ks2};
    const int R0[4] = {13, 15, 26, 6};
    const int R1[4] = {17, 29, 16, 24};
    uint32_t v0 = x0 + k0, v1 = x1 + k1;
    for (int i = 0; i < 5; i++) {
        for (int j = 0; j < 4; j++) {
            int r = (i % 2 == 0) ? R0[j] : R1[j];
            v0 += v1; v1 = rotl32(v1, r); v1 ^= v0;
        }
        v0 += kk[(i + 1) % 3];
        v1 += kk[(i + 2) % 3] + (uint32_t)(i + 1);
    }
    return TF2{v0, v1};
}

// key(42)->(0,42); keys=split(key,100); keys[99] from counts (98,198),(99,199)
constexpr TF2      S98 = tf2x32(0u, 42u, 98u, 198u);
constexpr TF2      S99 = tf2x32(0u, 42u, 99u, 199u);
constexpr uint32_t KLA = S98.b, KLB = S99.b;
constexpr TF2      SP0 = tf2x32(KLA, KLB, 0u, 2u);
constexpr TF2      SP1 = tf2x32(KLA, KLB, 1u, 3u);
constexpr uint32_t K1A = SP0.a, K1B = SP1.a;
constexpr uint32_t K2A = SP0.b, K2B = SP1.b;

__device__ __forceinline__ float tf_uniform(uint32_t ka, uint32_t kb, int n) {
    TF2 r = (n < 512) ? tf2x32(ka, kb, (uint32_t)n,         (uint32_t)(n + 512))
                      : tf2x32(ka, kb, (uint32_t)(n - 512), (uint32_t)n);
    uint32_t bits = (n < 512) ? r.a : r.b;
    return __uint_as_float((bits >> 9) | 0x3f800000u) - 1.0f;
}

// ======================= single persistent kernel ==========================
__global__ __launch_bounds__(256) void k_all(const float* __restrict__ cls,
                                             const float* __restrict__ labels,
                                             float* __restrict__ out) {
    __shared__ union {
        struct { float best[8][100]; int bi[8][100]; } pa;        // phase A
        float part[NC * 25];                                      // phase B partials
        struct { int idx[NI]; float u1[NI]; float u2[NI];
                 unsigned char sel[NI]; } tl;                     // tail
    } u;
    __shared__ int    sLab[TT];
    __shared__ float  sX99[NC];
    __shared__ double sGat[NC];
    __shared__ double sRed[8];
    __shared__ int    sN, sBg, sLast, sCnt;

    int tid  = threadIdx.x;
    int w    = tid >> 5;
    int lane = tid & 31;

    // ---------------- per-row loop via work queue ----------------
    for (;;) {
        if (tid == 0) sN = atomicAdd(&g_next, 1);
        __syncthreads();                    // also orders union reuse across rows
        int n = sN;
        if (n >= NI) break;

        if (tid < NC) sGat[tid] = 0.0;

        const float* lrow = labels + (size_t)n * ROW;
        const float* crow = cls    + (size_t)n * ROW;

        // ---- phase A: per-warp partial argmax over strided class subset ----
        if (lane < 25) {
            float b0 = -CUDART_INF_F, b1 = -CUDART_INF_F,
                  b2 = -CUDART_INF_F, b3 = -CUDART_INF_F;
            int i0 = 0, i1 = 0, i2 = 0, i3 = 0;
            #pragma unroll 4
            for (int c = w; c < NC; c += 8) {
                float4 v = __ldg((const float4*)(lrow + c * TT) + lane);
                if (v.x > b0) { b0 = v.x; i0 = c; }
                if (v.y > b1) { b1 = v.y; i1 = c; }
                if (v.z > b2) { b2 = v.z; i2 = c; }
                if (v.w > b3) { b3 = v.w; i3 = c; }
            }
            int t = lane * 4;
            u.pa.best[w][t + 0] = b0; u.pa.bi[w][t + 0] = i0;
            u.pa.best[w][t + 1] = b1; u.pa.bi[w][t + 1] = i1;
            u.pa.best[w][t + 2] = b2; u.pa.bi[w][t + 2] = i2;
            u.pa.best[w][t + 3] = b3; u.pa.bi[w][t + 3] = i3;
        }
        __syncthreads();

        // ---- combine partials; first-max tie-break (lower c wins) ----
        if (tid < TT) {
            float b = u.pa.best[0][tid]; int bi = u.pa.bi[0][tid];
            #pragma unroll
            for (int ww = 1; ww < 8; ww++) {
                float v = u.pa.best[ww][tid]; int c = u.pa.bi[ww][tid];
                if (v > b || (v == b && c < bi)) { b = v; bi = c; }
            }
            sLab[tid] = bi;
            if (tid == TT - 1) {
                int ib = (bi == NC - 1);
                sBg = ib;
                g_isbg[n] = (unsigned char)ib;
            }
        }
        __syncthreads();
        bool isbg = (sBg != 0);

        // ---- gather: sum_t x[n, lab[t], t] binned per class (smem) ----
        if (tid < TT) {
            int lb = sLab[tid];
            float x = __ldg(crow + (size_t)lb * TT + tid);
            atomicAdd(&sGat[lb], (double)x);
        }

        // ---- phase B: streamed softplus partials, no reductions in loop ----
        if (lane < 25) {
            #pragma unroll 4
            for (int c = w; c < NC; c += 8) {
                float4 x = __ldg((const float4*)(crow + c * TT) + lane);
                float m = fmaxf(x.x, 0.f) + fmaxf(x.y, 0.f)
                        + fmaxf(x.z, 0.f) + fmaxf(x.w, 0.f);
                float l = __log2f(1.f + __expf(-fabsf(x.x)))
                        + __log2f(1.f + __expf(-fabsf(x.y)))
                        + __log2f(1.f + __expf(-fabsf(x.z)))
                        + __log2f(1.f + __expf(-fabsf(x.w)));
                u.part[c * 25 + lane] = m + 0.69314718056f * l;   // hoisted ln2
                if (lane == 24) sX99[c] = x.w;                    // t = 99
            }
        }
        __syncthreads();

        // ---- final per-column pass ----
        int lab99 = sLab[TT - 1];
        double wv = 0.0;
        if (tid < NC) {
            float s = 0.f;
            #pragma unroll
            for (int i = 0; i < 25; i++) s += u.part[tid * 25 + i];
            float v = s - (float)sGat[tid];
            if (isbg) {
                g_v[n * NC + tid] = v;                 // wm decided in tail
            } else {
                float sg = 1.f / (1.f + __expf(-sX99[tid]));
                if (tid == lab99 || sg >= 0.3f) wv = (double)v;
            }
        }
        if (isbg) {
            if (tid == 0) g_part[n] = 0.0;
        } else {
            #pragma unroll
            for (int o = 16; o; o >>= 1) wv += __shfl_xor_sync(0xffffffffu, wv, o);
            if (lane == 0) sRed[w] = wv;
            __syncthreads();
            if (tid == 0) {
                double t = 0.0;
                #pragma unroll
                for (int i = 0; i < 8; i++) t += sRed[i];
                g_part[n] = t;
            }
        }
    }

    // ---------------- completion + tail in last-arriving block ----------------
    if (tid == 0) {
        __threadfence();
        int old = atomicAdd(&g_done, 1);
        sLast = (old == (int)gridDim.x - 1);
    }
    __syncthreads();
    if (!sLast) return;
    __threadfence();

    if (tid == 0) sCnt = 0;
    __syncthreads();

    // compact bg rows + uniforms
    for (int n = tid; n < NI; n += 256) {
        if (__ldcg(&g_isbg[n])) {
            int p = atomicAdd(&sCnt, 1);
            u.tl.idx[p] = n;
            u.tl.u1[p]  = tf_uniform(K1A, K1B, n);
            u.tl.u2[p]  = tf_uniform(K2A, K2B, n);
        }
    }
    __syncthreads();

    int nbg = sCnt;
    int kr  = nbg / 100;        // int(n_bg * 0.01)
    int kc  = nbg / 10;         // int(n_bg * 0.10)

    // stable-argsort ranks among bg rows
    for (int i = tid; i < nbg; i += 256) {
        float u1 = u.tl.u1[i], u2 = u.tl.u2[i];
        int   m  = u.tl.idx[i];
        int r1 = 0, r2 = 0;
        for (int j = 0; j < nbg; j++) {
            float a = u.tl.u1[j], b = u.tl.u2[j];
            int  mj = u.tl.idx[j];
            r1 += (a < u1) || (a == u1 && mj < m);
            r2 += (b < u2) || (b == u2 && mj < m);
        }
        u.tl.sel[i] = (unsigned char)((r1 < kr ? 2u : 0u) | (r2 < kc ? 4u : 0u));
    }
    __syncthreads();

    // sum per-row partials (fixed order -> deterministic)
    double acc = 0.0;
    for (int i = tid; i < NI; i += 256) acc += __ldcg(&g_part[i]);

    // bg contributions
    int total = nbg * NC;
    for (int q = tid; q < total; q += 256) {
        int i = q / NC;
        int c = q - i * NC;
        unsigned f = u.tl.sel[i];
        bool wm = (c >= 150) || ((f & 2u) && c < 50) ||
                  ((f & 4u) && c >= 50 && c < 150);
        if (wm) acc += (double)__ldcg(&g_v[u.tl.idx[i] * NC + c]);
    }

    #pragma unroll
    for (int o = 16; o; o >>= 1) acc += __shfl_xor_sync(0xffffffffu, acc, o);
    if (lane == 0) sRed[w] = acc;
    __syncthreads();
    if (tid == 0) {
        double s = 0.0;
        #pragma unroll
        for (int i = 0; i < 8; i++) s += sRed[i];
        out[0] = (float)(s * (1.0 / ((double)NI * (double)TT)));
        g_next = 0;             // reset queue + counter for next graph replay
        g_done = 0;
    }
}

// ======================= launcher ==========================================
extern "C" void kernel_launch(void* const* d_in, const int* in_sizes, int n_in,
                              void* d_out, int out_size) {
    const float* cls    = (const float*)d_in[0];   // [1024,201,100]
    const float* labels = (const float*)d_in[1];   // [1024,201,100]
    float* out = (float*)d_out;

    k_all<<<GRID, 256>>>(cls, labels, out);
}

// round 5
// speedup vs baseline: 1.2240x; 1.2240x over previous
#include <cuda_runtime.h>
#include <cstdint>
#include <math_constants.h>

#define NI   1024
#define NC   201
#define TT   100
#define ROW  (NC * TT)          // 20100
#define NQ4  (NC * 25)          // float4 per row = 5025
#define TOT4 (NI * NQ4)         // 5,145,600
#define GRID3 1184              // K3 grid (148 SM * 8)

// -------- scratch (no allocations; zero at module load) --------
__device__ double         g_acc;            // running total (reset by K3 tail)
__device__ unsigned char  g_wm[NI * NC];    // final weight mask bytes
__device__ unsigned char  g_isbg[NI];
__device__ float          g_bgG[NI * 3];    // bg gather partials: [rare, common, base]
__device__ int            g_done;           // K3 completion counter

// ======================= threefry2x32 (JAX-exact) =======================
__host__ __device__ constexpr uint32_t rotl32(uint32_t x, int r) {
    return (x << r) | (x >> (32 - r));
}
struct TF2 { uint32_t a, b; };

__host__ __device__ constexpr TF2 tf2x32(uint32_t k0, uint32_t k1,
                                         uint32_t x0, uint32_t x1) {
    uint32_t ks2 = k0 ^ k1 ^ 0x1BD11BDAu;
    uint32_t kk[3] = {k0, k1, ks2};
    const int R0[4] = {13, 15, 26, 6};
    const int R1[4] = {17, 29, 16, 24};
    uint32_t v0 = x0 + k0, v1 = x1 + k1;
    for (int i = 0; i < 5; i++) {
        for (int j = 0; j < 4; j++) {
            int r = (i % 2 == 0) ? R0[j] : R1[j];
            v0 += v1; v1 = rotl32(v1, r); v1 ^= v0;
        }
        v0 += kk[(i + 1) % 3];
        v1 += kk[(i + 2) % 3] + (uint32_t)(i + 1);
    }
    return TF2{v0, v1};
}

constexpr TF2      S98 = tf2x32(0u, 42u, 98u, 198u);
constexpr TF2      S99 = tf2x32(0u, 42u, 99u, 199u);
constexpr uint32_t KLA = S98.b, KLB = S99.b;
constexpr TF2      SP0 = tf2x32(KLA, KLB, 0u, 2u);
constexpr TF2      SP1 = tf2x32(KLA, KLB, 1u, 3u);
constexpr uint32_t K1A = SP0.a, K1B = SP1.a;
constexpr uint32_t K2A = SP0.b, K2B = SP1.b;

__device__ __forceinline__ float tf_uniform(uint32_t ka, uint32_t kb, int n) {
    TF2 r = (n < 512) ? tf2x32(ka, kb, (uint32_t)n,         (uint32_t)(n + 512))
                      : tf2x32(ka, kb, (uint32_t)(n - 512), (uint32_t)n);
    uint32_t bits = (n < 512) ? r.a : r.b;
    return __uint_as_float((bits >> 9) | 0x3f800000u) - 1.0f;
}

// ======================= K1: labels stream -> lab, wm, gather-dot ==========
__global__ __launch_bounds__(256) void k_lab(const float* __restrict__ labels,
                                             const float* __restrict__ cls) {
    __shared__ float  sBest[8][100];
    __shared__ int    sBi[8][100];
    __shared__ int    sLab[TT];
    __shared__ double sGat[NC];
    __shared__ float  sG3[3];
    __shared__ double sRed[8];

    int n    = blockIdx.x;
    int tid  = threadIdx.x;
    int w    = tid >> 5;
    int lane = tid & 31;

    if (tid < NC) sGat[tid] = 0.0;
    if (tid < 3)  sG3[tid]  = 0.f;

    const float* lrow = labels + (size_t)n * ROW;
    const float* crow = cls    + (size_t)n * ROW;

    // ---- per-warp partial argmax over strided class subset ----
    if (lane < 25) {
        float b0 = -CUDART_INF_F, b1 = -CUDART_INF_F,
              b2 = -CUDART_INF_F, b3 = -CUDART_INF_F;
        int i0 = 0, i1 = 0, i2 = 0, i3 = 0;
        #pragma unroll 4
        for (int c = w; c < NC; c += 8) {
            float4 v = __ldg((const float4*)(lrow + c * TT) + lane);
            if (v.x > b0) { b0 = v.x; i0 = c; }
            if (v.y > b1) { b1 = v.y; i1 = c; }
            if (v.z > b2) { b2 = v.z; i2 = c; }
            if (v.w > b3) { b3 = v.w; i3 = c; }
        }
        int t = lane * 4;
        sBest[w][t + 0] = b0; sBi[w][t + 0] = i0;
        sBest[w][t + 1] = b1; sBi[w][t + 1] = i1;
        sBest[w][t + 2] = b2; sBi[w][t + 2] = i2;
        sBest[w][t + 3] = b3; sBi[w][t + 3] = i3;
    }
    __syncthreads();

    // ---- combine partials; first-max tie-break (lower c wins) ----
    if (tid < TT) {
        float b = sBest[0][tid]; int bi = sBi[0][tid];
        #pragma unroll
        for (int ww = 1; ww < 8; ww++) {
            float v = sBest[ww][tid]; int c = sBi[ww][tid];
            if (v > b || (v == b && c < bi)) { b = v; bi = c; }
        }
        sLab[tid] = bi;
    }
    __syncthreads();

    int  lab99 = sLab[TT - 1];
    bool isbg  = (lab99 == NC - 1);
    if (tid == 0) g_isbg[n] = (unsigned char)isbg;

    // ---- gather: sum_t x[n, lab[t], t] binned per class ----
    if (tid < TT) {
        int lb = sLab[tid];
        atomicAdd(&sGat[lb], (double)__ldg(crow + (size_t)lb * TT + tid));
    }
    __syncthreads();

    // ---- per-class: wm (non-bg) + gather dot; bg -> range partials ----
    float neg = 0.f;
    if (tid < NC) {
        float g = (float)sGat[tid];
        if (!isbg) {
            float x99 = __ldg(crow + (size_t)tid * TT + 99);
            float sg  = 1.f / (1.f + __expf(-x99));
            bool wm = (tid == lab99) || (sg >= 0.3f);
            g_wm[n * NC + tid] = (unsigned char)wm;
            if (wm) neg = g;
        } else if (g != 0.f) {
            int r = (tid >= 150) ? 2 : (tid >= 50 ? 1 : 0);
            atomicAdd(&sG3[r], g);
        }
    }

    // block reduce of gather dot (non-bg)
    #pragma unroll
    for (int o = 16; o; o >>= 1) neg += __shfl_xor_sync(0xffffffffu, neg, o);
    if (lane == 0) sRed[w] = (double)neg;
    __syncthreads();
    if (tid == 0) {
        if (!isbg) {
            double s = 0.0;
            #pragma unroll
            for (int i = 0; i < 8; i++) s += sRed[i];
            atomicAdd(&g_acc, -s);
        }
    }
    if (isbg && tid < 3) g_bgG[n * 3 + tid] = sG3[tid];
}

// ======================= K2: bg selection + bg wm/gather ===================
__global__ __launch_bounds__(256) void k_sel() {
    __shared__ int           idx[NI];
    __shared__ float         u1a[NI];
    __shared__ float         u2a[NI];
    __shared__ unsigned char sel[NI];
    __shared__ int           cnt;
    __shared__ double        dsum;

    int tid = threadIdx.x;
    if (tid == 0) { cnt = 0; dsum = 0.0; }
    __syncthreads();

    for (int n = tid; n < NI; n += 256) {
        if (g_isbg[n]) {
            int p = atomicAdd(&cnt, 1);
            idx[p] = n;
            u1a[p] = tf_uniform(K1A, K1B, n);
            u2a[p] = tf_uniform(K2A, K2B, n);
        }
    }
    __syncthreads();

    int nbg = cnt;
    int kr  = nbg / 100;
    int kc  = nbg / 10;

    // stable-argsort ranks among bg rows
    for (int i = tid; i < nbg; i += 256) {
        float u1 = u1a[i], u2 = u2a[i];
        int   m  = idx[i];
        int r1 = 0, r2 = 0;
        for (int j = 0; j < nbg; j++) {
            float a = u1a[j], b = u2a[j];
            int  mj = idx[j];
            r1 += (a < u1) || (a == u1 && mj < m);
            r2 += (b < u2) || (b == u2 && mj < m);
        }
        sel[i] = (unsigned char)((r1 < kr ? 2u : 0u) | (r2 < kc ? 4u : 0u));
    }
    __syncthreads();

    // bg gather contributions
    double a = 0.0;
    for (int i = tid; i < nbg; i += 256) {
        const float* G = &g_bgG[idx[i] * 3];
        unsigned f = sel[i];
        a += (double)G[2];
        if (f & 2u) a += (double)G[0];
        if (f & 4u) a += (double)G[1];
    }
    if (a != 0.0) atomicAdd(&dsum, a);

    // bg wm bytes
    for (int q = tid; q < nbg * NC; q += 256) {
        int i = q / NC;
        int c = q - i * NC;
        unsigned f = sel[i];
        bool wm = (c >= 150) || ((f & 2u) && c < 50) ||
                  ((f & 4u) && c >= 50 && c < 150);
        g_wm[idx[i] * NC + c] = (unsigned char)wm;
    }
    __syncthreads();
    if (tid == 0) atomicAdd(&g_acc, -dsum);
}

// ======================= K3: flat softplus stream + finalize ===============
__global__ __launch_bounds__(256) void k_sp(const float* __restrict__ cls,
                                            float* __restrict__ out) {
    __shared__ double sRed[8];
    __shared__ int    sLast;

    int tid  = threadIdx.x;
    int w    = tid >> 5;
    int lane = tid & 31;
    int stride = gridDim.x * 256;

    float acc = 0.f;
    for (int q = blockIdx.x * 256 + tid; q < TOT4; q += stride) {
        if (g_wm[q / 25]) {                       // wm known: skip dead classes
            float4 x = __ldg((const float4*)cls + q);
            float m = fmaxf(x.x, 0.f) + fmaxf(x.y, 0.f)
                    + fmaxf(x.z, 0.f) + fmaxf(x.w, 0.f);
            float l = __log2f(1.f + __expf(-fabsf(x.x)))
                    + __log2f(1.f + __expf(-fabsf(x.y)))
                    + __log2f(1.f + __expf(-fabsf(x.z)))
                    + __log2f(1.f + __expf(-fabsf(x.w)));
            acc += m + 0.69314718056f * l;
        }
    }

    double d = (double)acc;
    #pragma unroll
    for (int o = 16; o; o >>= 1) d += __shfl_xor_sync(0xffffffffu, d, o);
    if (lane == 0) sRed[w] = d;
    __syncthreads();
    if (tid == 0) {
        double s = 0.0;
        #pragma unroll
        for (int i = 0; i < 8; i++) s += sRed[i];
        atomicAdd(&g_acc, s);
        __threadfence();
        int old = atomicAdd(&g_done, 1);
        sLast = (old == (int)gridDim.x - 1);
    }
    __syncthreads();
    if (sLast && tid == 0) {
        double tot = atomicAdd(&g_acc, 0.0);      // all contributions visible
        out[0] = (float)(tot * (1.0 / ((double)NI * (double)TT)));
        g_acc  = 0.0;                             // reset for next graph replay
        g_done = 0;
    }
}

// ======================= launcher ==========================================
extern "C" void kernel_launch(void* const* d_in, const int* in_sizes, int n_in,
                              void* d_out, int out_size) {
    const float* cls    = (const float*)d_in[0];   // [1024,201,100]
    const float* labels = (const float*)d_in[1];   // [1024,201,100]
    float* out = (float*)d_out;

    k_lab<<<NI, 256>>>(labels, cls);
    k_sel<<<1, 256>>>();
    k_sp <<<GRID3, 256>>>(cls, out);
}